// round 3
// baseline (speedup 1.0000x reference)
#include <cuda_runtime.h>

// Banded DTW (Sakoe-Chiba w=1) as a min-plus (tropical) 3x3 matrix reduction.
//
// Per-row recurrence on carry (p0,p1,p2) with costs a=|o_i - t_{i-2}|,
// b=|o_i - t_{i-1}|, c=|o_i - t_i| (a=INF at i=1, c=INF at i=n):
//   n0 = a + min(p0,p1)
//   n1 = b + min(n0, min(p1,p2))
//   n2 = c + min(n1, p2)
// This is min-plus linear -> each row is a 3x3 tropical matrix; composition is
// associative -> parallel ordered reduction. Answer = (M_total (x) (INF,0,INF))[1]
// = M_total[1][1].

#define NTHREADS 128
#define NBLOCKS  128

__device__ float g_bmats[NBLOCKS * 9];

__device__ __forceinline__ float finf() { return __int_as_float(0x7f800000); }

// C = L o E  (E = earlier chunk, L = later chunk): C[i][j] = min_k L[i][k] + E[k][j]
__device__ __forceinline__ void mp_combine(const float* __restrict__ L,
                                           const float* __restrict__ E,
                                           float* __restrict__ C) {
#pragma unroll
    for (int i = 0; i < 3; ++i) {
#pragma unroll
        for (int j = 0; j < 3; ++j) {
            float v = L[i * 3 + 0] + E[0 + j];
            v = fminf(v, L[i * 3 + 1] + E[3 + j]);
            v = fminf(v, L[i * 3 + 2] + E[6 + j]);
            C[i * 3 + j] = v;
        }
    }
}

// Apply one DTW row-step (costs a,b,c) to all three columns of M (M row-major).
__device__ __forceinline__ void step_cols(float M[9], float a, float b, float c) {
#pragma unroll
    for (int j = 0; j < 3; ++j) {
        float p0 = M[0 + j], p1 = M[3 + j], p2 = M[6 + j];
        float n0 = a + fminf(p0, p1);
        float n1 = b + fminf(n0, fminf(p1, p2));
        float n2 = c + fminf(n1, p2);
        M[0 + j] = n0; M[3 + j] = n1; M[6 + j] = n2;
    }
}

// Order-preserving in-block tree reduction over shared matrices (non-commutative!).
// Pairs ADJACENT elements: res[t] = smat[2t+1] o smat[2t].
template <int N>
__device__ __forceinline__ void block_reduce(float (*smat)[9], int tid) {
    int active = N;
    while (active > 1) {
        active >>= 1;
        __syncthreads();
        float tmp[9];
        const bool act = tid < active;
        if (act) mp_combine(smat[2 * tid + 1], smat[2 * tid], tmp);
        __syncthreads();
        if (act) {
#pragma unroll
            for (int q = 0; q < 9; ++q) smat[tid][q] = tmp[q];
        }
    }
    __syncthreads();
}

__global__ void __launch_bounds__(NTHREADS) dtw_phase1(
    const float* __restrict__ oseq, const float* __restrict__ tgt,
    int n, int chunk) {
    const float INF = finf();
    const int tid = threadIdx.x;
    const int gid = blockIdx.x * NTHREADS + tid;
    const long s0 = (long)gid * chunk;  // first step handled is i = s0 + 1 (1-based)

    // chunk matrix, initialized to min-plus identity
    float M[9] = {0.f, INF, INF,  INF, 0.f, INF,  INF, INF, 0.f};

    if (chunk == 8 && s0 + 8 <= n && ((s0 & 3) == 0)) {
        // fast path: vectorized loads, fully unrolled 8 steps
        float4 o0 = *(const float4*)(oseq + s0);
        float4 o1 = *(const float4*)(oseq + s0 + 4);
        float4 t0 = *(const float4*)(tgt + s0);
        float4 t1 = *(const float4*)(tgt + s0 + 4);
        float o[8] = {o0.x, o0.y, o0.z, o0.w, o1.x, o1.y, o1.z, o1.w};
        float t[10];
        t[0] = (s0 >= 1) ? __ldg(tgt + s0 - 1) : 0.f;   // t_{i-2} for i=s0+1 (unused if i<2)
        t[1] = t0.x; t[2] = t0.y; t[3] = t0.z; t[4] = t0.w;
        t[5] = t1.x; t[6] = t1.y; t[7] = t1.z; t[8] = t1.w;
        t[9] = (s0 + 8 < n) ? __ldg(tgt + s0 + 8) : 0.f; // t_i for i=s0+8 (unused if i>n-1)
#pragma unroll
        for (int k = 0; k < 8; ++k) {
            const long i = s0 + 1 + k;
            float a = (i >= 2)     ? fabsf(o[k] - t[k])     : INF;
            float b =                fabsf(o[k] - t[k + 1]);
            float c = (i <= n - 1) ? fabsf(o[k] - t[k + 2]) : INF;
            step_cols(M, a, b, c);
        }
    } else {
        // generic guarded path
        for (int k = 0; k < chunk; ++k) {
            const long i = s0 + 1 + k;
            if (i > n) break;
            float o = __ldg(oseq + (i - 1));
            float a = (i >= 2)     ? fabsf(o - __ldg(tgt + (i - 2))) : INF;
            float b =                fabsf(o - __ldg(tgt + (i - 1)));
            float c = (i <= n - 1) ? fabsf(o - __ldg(tgt + i))       : INF;
            step_cols(M, a, b, c);
        }
    }

    __shared__ float smat[NTHREADS][9];
#pragma unroll
    for (int q = 0; q < 9; ++q) smat[tid][q] = M[q];

    block_reduce<NTHREADS>(smat, tid);

    if (tid == 0) {
#pragma unroll
        for (int q = 0; q < 9; ++q) g_bmats[blockIdx.x * 9 + q] = smat[0][q];
    }
}

__global__ void __launch_bounds__(NBLOCKS) dtw_phase2(float* __restrict__ out) {
    __shared__ float smat[NBLOCKS][9];
    const int tid = threadIdx.x;
#pragma unroll
    for (int q = 0; q < 9; ++q) smat[tid][q] = g_bmats[tid * 9 + q];

    block_reduce<NBLOCKS>(smat, tid);

    if (tid == 0) {
        // v_init = (INF, 0, INF); answer = (M (x) v)[1] = M[1][1]
        out[0] = smat[0][4];
    }
}

extern "C" void kernel_launch(void* const* d_in, const int* in_sizes, int n_in,
                              void* d_out, int out_size) {
    const float* oseq = (const float*)d_in[0];
    const float* tgt  = (const float*)d_in[1];
    const int n = in_sizes[0];

    const int P = NTHREADS * NBLOCKS;
    const int chunk = (n + P - 1) / P;

    dtw_phase1<<<NBLOCKS, NTHREADS>>>(oseq, tgt, n, chunk);
    dtw_phase2<<<1, NBLOCKS>>>((float*)d_out);
}

// round 4
// speedup vs baseline: 1.0448x; 1.0448x over previous
#include <cuda_runtime.h>

// Banded DTW (Sakoe-Chiba w=1) as a min-plus (tropical) 3x3 matrix reduction,
// fused into a single kernel via the last-block-done pattern.
//
// Per-row recurrence on carry (p0,p1,p2) with costs a=|o_i - t_{i-2}|,
// b=|o_i - t_{i-1}|, c=|o_i - t_i| (a=INF at i=1, c=INF at i=n):
//   n0 = a + min(p0,p1)
//   n1 = b + min(n0, min(p1,p2))
//   n2 = c + min(n1, p2)
// Min-plus linear -> each row is a 3x3 tropical matrix; composition is
// associative -> parallel ordered reduction. Answer = M_total[1][1].

#define NTHREADS 128
#define NBLOCKS  128

__device__ float g_bmats[NBLOCKS * 9];
__device__ unsigned int g_ticket = 0;

__device__ __forceinline__ float finf() { return __int_as_float(0x7f800000); }

struct Mat {
    float m[9];  // row-major
};

// C = L o E  (E = earlier chunk, L = later chunk): C[i][j] = min_k L[i][k] + E[k][j]
__device__ __forceinline__ Mat mp_combine(const Mat& L, const Mat& E) {
    Mat C;
#pragma unroll
    for (int i = 0; i < 3; ++i) {
#pragma unroll
        for (int j = 0; j < 3; ++j) {
            float v = L.m[i * 3 + 0] + E.m[0 + j];
            v = fminf(v, L.m[i * 3 + 1] + E.m[3 + j]);
            v = fminf(v, L.m[i * 3 + 2] + E.m[6 + j]);
            C.m[i * 3 + j] = v;
        }
    }
    return C;
}

// Apply one DTW row-step (costs a,b,c) to all three columns of M.
__device__ __forceinline__ void step_cols(Mat& M, float a, float b, float c) {
#pragma unroll
    for (int j = 0; j < 3; ++j) {
        float p0 = M.m[0 + j], p1 = M.m[3 + j], p2 = M.m[6 + j];
        float n0 = a + fminf(p0, p1);
        float n1 = b + fminf(n0, fminf(p1, p2));
        float n2 = c + fminf(n1, p2);
        M.m[0 + j] = n0; M.m[3 + j] = n1; M.m[6 + j] = n2;
    }
}

// Order-preserving reduction across the full 128-thread block.
// Thread t holds the matrix for segment t (t ascending = later in sequence).
// Result (product over ALL segments, later-o-earlier) lands in thread 0's M.
// Uses warp shuffles (no barriers) within warps, shared mem across 4 warps.
__device__ __forceinline__ void block_reduce_mat(Mat& M, int tid) {
    const int lane = tid & 31;
    const int warp = tid >> 5;

    // In-warp ordered tree: at stride s, lanes t ≡ 0 (mod 2s) do M_t = M_{t+s} o M_t.
#pragma unroll
    for (int s = 1; s < 32; s <<= 1) {
        Mat other;
#pragma unroll
        for (int q = 0; q < 9; ++q)
            other.m[q] = __shfl_down_sync(0xffffffffu, M.m[q], s);
        if ((lane & (2 * s - 1)) == 0) M = mp_combine(other, M);
    }

    __shared__ Mat swarp[NTHREADS / 32];
    if (lane == 0) swarp[warp] = M;
    __syncthreads();

    if (tid == 0) {
        Mat acc = swarp[0];
#pragma unroll
        for (int w = 1; w < NTHREADS / 32; ++w)
            acc = mp_combine(swarp[w], acc);
        M = acc;
    }
}

__global__ void __launch_bounds__(NTHREADS) dtw_fused(
    const float* __restrict__ oseq, const float* __restrict__ tgt,
    int n, int chunk, float* __restrict__ out) {
    const float INF = finf();
    const int tid = threadIdx.x;
    const int gid = blockIdx.x * NTHREADS + tid;
    const long s0 = (long)gid * chunk;  // first step handled is i = s0 + 1 (1-based)

    // chunk matrix, initialized to min-plus identity
    Mat M;
    M.m[0] = 0.f; M.m[1] = INF; M.m[2] = INF;
    M.m[3] = INF; M.m[4] = 0.f; M.m[5] = INF;
    M.m[6] = INF; M.m[7] = INF; M.m[8] = 0.f;

    if (chunk == 8 && s0 + 8 <= n && ((s0 & 3) == 0)) {
        // fast path: vectorized loads, fully unrolled 8 steps
        float4 o0 = *(const float4*)(oseq + s0);
        float4 o1 = *(const float4*)(oseq + s0 + 4);
        float4 t0 = *(const float4*)(tgt + s0);
        float4 t1 = *(const float4*)(tgt + s0 + 4);
        float o[8] = {o0.x, o0.y, o0.z, o0.w, o1.x, o1.y, o1.z, o1.w};
        float t[10];
        t[0] = (s0 >= 1) ? __ldg(tgt + s0 - 1) : 0.f;    // t_{i-2} for i=s0+1
        t[1] = t0.x; t[2] = t0.y; t[3] = t0.z; t[4] = t0.w;
        t[5] = t1.x; t[6] = t1.y; t[7] = t1.z; t[8] = t1.w;
        t[9] = (s0 + 8 < n) ? __ldg(tgt + s0 + 8) : 0.f; // t_i for i=s0+8
#pragma unroll
        for (int k = 0; k < 8; ++k) {
            const long i = s0 + 1 + k;
            float a = (i >= 2)     ? fabsf(o[k] - t[k])     : INF;
            float b =                fabsf(o[k] - t[k + 1]);
            float c = (i <= n - 1) ? fabsf(o[k] - t[k + 2]) : INF;
            step_cols(M, a, b, c);
        }
    } else {
        // generic guarded path
        for (int k = 0; k < chunk; ++k) {
            const long i = s0 + 1 + k;
            if (i > n) break;
            float o = __ldg(oseq + (i - 1));
            float a = (i >= 2)     ? fabsf(o - __ldg(tgt + (i - 2))) : INF;
            float b =                fabsf(o - __ldg(tgt + (i - 1)));
            float c = (i <= n - 1) ? fabsf(o - __ldg(tgt + i))       : INF;
            step_cols(M, a, b, c);
        }
    }

    // In-block ordered reduction -> thread 0 holds the block matrix.
    block_reduce_mat(M, tid);

    // Publish block matrix, then last block to finish does the final reduce.
    __shared__ unsigned int s_ticket;
    if (tid == 0) {
#pragma unroll
        for (int q = 0; q < 9; ++q) g_bmats[blockIdx.x * 9 + q] = M.m[q];
        __threadfence();
        s_ticket = atomicAdd(&g_ticket, 1u);
    }
    __syncthreads();

    if (s_ticket == NBLOCKS - 1) {
        __threadfence();  // acquire: see all blocks' g_bmats writes
        Mat B;
#pragma unroll
        for (int q = 0; q < 9; ++q) B.m[q] = g_bmats[tid * 9 + q];

        block_reduce_mat(B, tid);

        if (tid == 0) {
            // v_init = (INF, 0, INF); answer = (M (x) v)[1] = M[1][1]
            out[0] = B.m[4];
            g_ticket = 0;  // reset for next graph replay
        }
    }
}

extern "C" void kernel_launch(void* const* d_in, const int* in_sizes, int n_in,
                              void* d_out, int out_size) {
    const float* oseq = (const float*)d_in[0];
    const float* tgt  = (const float*)d_in[1];
    const int n = in_sizes[0];

    const int P = NTHREADS * NBLOCKS;
    const int chunk = (n + P - 1) / P;

    dtw_fused<<<NBLOCKS, NTHREADS>>>(oseq, tgt, n, chunk, (float*)d_out);
}